// round 1
// baseline (speedup 1.0000x reference)
#include <cuda_runtime.h>
#include <math.h>

#define B  8
#define TQ 128
#define TK 512
#define DD 256
#define HH 256

// Scratch (no allocations allowed)
__device__ float g_qp[B * TQ * HH];     // 1 MB
__device__ float g_kp[B * TK * HH];     // 4 MB
__device__ float g_attn[B * TQ * TK];   // 2 MB (scores, then attn in place)

__device__ __forceinline__ float tanh_fast(float x) {
    float y;
    asm("tanh.approx.f32 %0, %1;" : "=f"(y) : "f"(x));
    return y;
}

// ---------------------------------------------------------------------------
// Projection GEMM: C[M,256] = A[M,256] @ W[256,256]
// block = 64x64 tile, 256 threads, 4x4 micro-tile, k-chunk 16
// which: 0 -> g_qp, 1 -> g_kp
// ---------------------------------------------------------------------------
__global__ __launch_bounds__(256) void proj_kernel(
    const float* __restrict__ A, const float* __restrict__ W, int which) {
    __shared__ float As[16][64];   // [k][m]
    __shared__ float Bs[16][64];   // [k][n]
    float* __restrict__ C = which ? g_kp : g_qp;

    const int t  = threadIdx.x;
    const int bm = blockIdx.y * 64;
    const int bn = blockIdx.x * 64;
    const int tx = t % 16;         // n group
    const int ty = t / 16;         // m group

    float acc[4][4] = {};

    for (int k0 = 0; k0 < 256; k0 += 16) {
        // A tile: 64 rows x 16 k
        {
            int row = t / 4, kk = (t % 4) * 4;
            float4 v = *(const float4*)(A + (size_t)(bm + row) * 256 + k0 + kk);
            As[kk + 0][row] = v.x;
            As[kk + 1][row] = v.y;
            As[kk + 2][row] = v.z;
            As[kk + 3][row] = v.w;
        }
        // W tile: 16 k x 64 n
        {
            int kk = t / 16, col = (t % 16) * 4;
            *(float4*)&Bs[kk][col] =
                *(const float4*)(W + (size_t)(k0 + kk) * 256 + bn + col);
        }
        __syncthreads();
        #pragma unroll
        for (int kk = 0; kk < 16; kk++) {
            float4 a4 = *(const float4*)&As[kk][ty * 4];
            float4 b4 = *(const float4*)&Bs[kk][tx * 4];
            float a[4] = {a4.x, a4.y, a4.z, a4.w};
            float bb[4] = {b4.x, b4.y, b4.z, b4.w};
            #pragma unroll
            for (int i = 0; i < 4; i++)
                #pragma unroll
                for (int j = 0; j < 4; j++)
                    acc[i][j] += a[i] * bb[j];
        }
        __syncthreads();
    }
    #pragma unroll
    for (int i = 0; i < 4; i++) {
        float4 v = make_float4(acc[i][0], acc[i][1], acc[i][2], acc[i][3]);
        *(float4*)(C + (size_t)(bm + ty * 4 + i) * 256 + bn + tx * 4) = v;
    }
}

// ---------------------------------------------------------------------------
// Scores: s[b,q,k] = sum_h tanh(qp[b,q,h] + kp[b,k,h]) * wv[h]
// block = (b, 16 q, 64 k); 256 threads: kl = t%64, qg = t/64 handles 4 q
// h processed in 4 chunks of 64; kp load amortized over 4 q per thread.
// ---------------------------------------------------------------------------
__global__ __launch_bounds__(256) void scores_kernel(const float* __restrict__ wv) {
    __shared__ float qp_s[16][68];
    __shared__ float kp_s[64][68];
    __shared__ float wv_s[HH];

    const int t  = threadIdx.x;
    const int kt = blockIdx.x;   // 0..7 (k tile of 64)
    const int qt = blockIdx.y;   // 0..7 (q tile of 16)
    const int b  = blockIdx.z;   // 0..7
    const int kl = t % 64;       // k within tile (contiguous within warp)
    const int qg = t / 64;       // 0..3 -> q rows qg*4 .. qg*4+3 (warp-uniform)

    if (t < HH) wv_s[t] = wv[t];

    const float* qp_base = g_qp + ((size_t)b * TQ + qt * 16) * HH;
    const float* kp_base = g_kp + ((size_t)b * TK + kt * 64) * HH;

    float acc[4] = {0.f, 0.f, 0.f, 0.f};

    for (int c = 0; c < 4; c++) {
        const int h0 = c * 64;
        __syncthreads();
        {
            int row = t / 16, col = (t % 16) * 4;
            *(float4*)&qp_s[row][col] =
                *(const float4*)(qp_base + (size_t)row * HH + h0 + col);
            #pragma unroll
            for (int j = 0; j < 4; j++) {
                int kr = row + j * 16;
                *(float4*)&kp_s[kr][col] =
                    *(const float4*)(kp_base + (size_t)kr * HH + h0 + col);
            }
        }
        __syncthreads();
        #pragma unroll
        for (int h4 = 0; h4 < 16; h4++) {
            float4 kv  = *(const float4*)&kp_s[kl][h4 * 4];
            float4 wvv = *(const float4*)&wv_s[h0 + h4 * 4];
            #pragma unroll
            for (int i = 0; i < 4; i++) {
                float4 qv = *(const float4*)&qp_s[qg * 4 + i][h4 * 4];
                acc[i] += tanh_fast(qv.x + kv.x) * wvv.x;
                acc[i] += tanh_fast(qv.y + kv.y) * wvv.y;
                acc[i] += tanh_fast(qv.z + kv.z) * wvv.z;
                acc[i] += tanh_fast(qv.w + kv.w) * wvv.w;
            }
        }
    }
    #pragma unroll
    for (int i = 0; i < 4; i++) {
        int q = qt * 16 + qg * 4 + i;
        g_attn[((size_t)b * TQ + q) * TK + kt * 64 + kl] = acc[i];
    }
}

// ---------------------------------------------------------------------------
// Masked softmax over TK=512, in place on g_attn. One block per (b,q) row.
// valid_lens[b] >= 1 always (randint(1, Tk+1)), so never fully masked.
// ---------------------------------------------------------------------------
__global__ __launch_bounds__(256) void softmax_kernel(const int* __restrict__ valid_lens) {
    const int row = blockIdx.x;        // b*TQ + q
    const int b   = row / TQ;
    const int t   = threadIdx.x;
    const int vl  = valid_lens[b];

    float* s = g_attn + (size_t)row * TK;
    float v0 = s[t];
    float v1 = s[t + 256];
    bool  m0 = t < vl;
    bool  m1 = (t + 256) < vl;

    __shared__ float red_max[8];
    __shared__ float red_sum[8];

    float lmax = fmaxf(m0 ? v0 : -INFINITY, m1 ? v1 : -INFINITY);
    #pragma unroll
    for (int o = 16; o > 0; o >>= 1)
        lmax = fmaxf(lmax, __shfl_xor_sync(0xffffffff, lmax, o));
    if ((t & 31) == 0) red_max[t >> 5] = lmax;
    __syncthreads();
    float bmax = red_max[0];
    #pragma unroll
    for (int i = 1; i < 8; i++) bmax = fmaxf(bmax, red_max[i]);

    float e0 = m0 ? __expf(v0 - bmax) : 0.f;
    float e1 = m1 ? __expf(v1 - bmax) : 0.f;

    float lsum = e0 + e1;
    #pragma unroll
    for (int o = 16; o > 0; o >>= 1)
        lsum += __shfl_xor_sync(0xffffffff, lsum, o);
    if ((t & 31) == 0) red_sum[t >> 5] = lsum;
    __syncthreads();
    float bsum = 0.f;
    #pragma unroll
    for (int i = 0; i < 8; i++) bsum += red_sum[i];

    float inv = 1.0f / bsum;
    s[t]       = e0 * inv;
    s[t + 256] = e1 * inv;
}

// ---------------------------------------------------------------------------
// out[b,q,d] = sum_k attn[b,q,k] * values[b,k,d]
// block = (qt of 8 q, b); 256 threads: dl=(t%64)*4, qg=t/64 handles 2 q
// ---------------------------------------------------------------------------
__global__ __launch_bounds__(256) void av_kernel(
    const float* __restrict__ values, float* __restrict__ out) {
    __shared__ float attn_s[8][512];   // 16 KB

    const int t  = threadIdx.x;
    const int qt = blockIdx.x;         // 0..15 (8 q per tile)
    const int b  = blockIdx.y;
    const int dl = (t % 64) * 4;
    const int qg = t / 64;             // 0..3 -> q rows qg*2, qg*2+1

    {
        const float4* src = (const float4*)(g_attn + ((size_t)b * TQ + qt * 8) * TK);
        float4* dst = (float4*)&attn_s[0][0];
        #pragma unroll
        for (int j = 0; j < 4; j++) dst[t + 256 * j] = src[t + 256 * j];
    }
    __syncthreads();

    float acc0[4] = {};
    float acc1[4] = {};
    const float* vbase = values + (size_t)b * TK * DD;

    for (int k4 = 0; k4 < 128; k4++) {
        float4 a0 = *(const float4*)&attn_s[qg * 2 + 0][k4 * 4];
        float4 a1 = *(const float4*)&attn_s[qg * 2 + 1][k4 * 4];
        float av0[4] = {a0.x, a0.y, a0.z, a0.w};
        float av1[4] = {a1.x, a1.y, a1.z, a1.w};
        #pragma unroll
        for (int kk = 0; kk < 4; kk++) {
            float4 v = *(const float4*)(vbase + (size_t)(k4 * 4 + kk) * DD + dl);
            acc0[0] += av0[kk] * v.x; acc0[1] += av0[kk] * v.y;
            acc0[2] += av0[kk] * v.z; acc0[3] += av0[kk] * v.w;
            acc1[0] += av1[kk] * v.x; acc1[1] += av1[kk] * v.y;
            acc1[2] += av1[kk] * v.z; acc1[3] += av1[kk] * v.w;
        }
    }

    {
        int q = qt * 8 + qg * 2;
        *(float4*)(out + ((size_t)b * TQ + q) * DD + dl) =
            make_float4(acc0[0], acc0[1], acc0[2], acc0[3]);
        *(float4*)(out + ((size_t)b * TQ + q + 1) * DD + dl) =
            make_float4(acc1[0], acc1[1], acc1[2], acc1[3]);
    }
}

// ---------------------------------------------------------------------------
// Inputs (metadata order): queries, keys, values, valid_lens, Wq, Wk, wv
// ---------------------------------------------------------------------------
extern "C" void kernel_launch(void* const* d_in, const int* in_sizes, int n_in,
                              void* d_out, int out_size) {
    const float* queries    = (const float*)d_in[0];
    const float* keys       = (const float*)d_in[1];
    const float* values     = (const float*)d_in[2];
    const int*   valid_lens = (const int*)d_in[3];
    const float* Wq         = (const float*)d_in[4];
    const float* Wk         = (const float*)d_in[5];
    const float* wv         = (const float*)d_in[6];
    float*       out        = (float*)d_out;

    // q projection: M = B*TQ = 1024 -> grid (256/64, 1024/64)
    proj_kernel<<<dim3(4, 16), 256>>>(queries, Wq, 0);
    // k projection: M = B*TK = 4096
    proj_kernel<<<dim3(4, 64), 256>>>(keys, Wk, 1);
    // scores: (k-tiles, q-tiles, b)
    scores_kernel<<<dim3(8, 8, 8), 256>>>(wv);
    // masked softmax, one block per row
    softmax_kernel<<<B * TQ, 256>>>(valid_lens);
    // attention @ values
    av_kernel<<<dim3(16, 8), 256>>>(values, out);
}

// round 2
// speedup vs baseline: 1.0925x; 1.0925x over previous
#include <cuda_runtime.h>
#include <math.h>

#define B  8
#define TQ 128
#define TK 512
#define DD 256
#define HH 256

// Scratch (no allocations allowed)
__device__ float g_qp[B * TQ * HH];     // 1 MB
__device__ float g_kp[B * TK * HH];     // 4 MB
__device__ float g_attn[B * TQ * TK];   // 2 MB (raw scores)

typedef unsigned long long u64;

__device__ __forceinline__ float tanh_fast(float x) {
    float y;
    asm("tanh.approx.f32 %0, %1;" : "=f"(y) : "f"(x));
    return y;
}
__device__ __forceinline__ u64 ffma2(u64 a, u64 b, u64 c) {
    u64 d;
    asm("fma.rn.f32x2 %0, %1, %2, %3;" : "=l"(d) : "l"(a), "l"(b), "l"(c));
    return d;
}
__device__ __forceinline__ u64 fadd2(u64 a, u64 b) {
    u64 d;
    asm("add.rn.f32x2 %0, %1, %2;" : "=l"(d) : "l"(a), "l"(b));
    return d;
}
__device__ __forceinline__ u64 pack2(float lo, float hi) {
    u64 r;
    asm("mov.b64 %0, {%1, %2};" : "=l"(r) : "f"(lo), "f"(hi));
    return r;
}
__device__ __forceinline__ float2 unpack2(u64 v) {
    float lo, hi;
    asm("mov.b64 {%0, %1}, %2;" : "=f"(lo), "=f"(hi) : "l"(v));
    return make_float2(lo, hi);
}
__device__ __forceinline__ float sum2(u64 v) {
    float2 f = unpack2(v);
    return f.x + f.y;
}

// ---------------------------------------------------------------------------
// Combined projection GEMM: both q@Wq and k@Wk in one launch.
// blockIdx.y < 16 -> q rows, else k rows. 64x64 tile, 256 thr, 4x4 micro-tile
// with packed FFMA2 (2 MACs per fma-pipe issue).
// ---------------------------------------------------------------------------
__global__ __launch_bounds__(256) void proj_kernel(
    const float* __restrict__ q, const float* __restrict__ k,
    const float* __restrict__ Wq, const float* __restrict__ Wk) {
    __shared__ float As[16][64];   // [k][m]
    __shared__ float Bs[16][64];   // [k][n]

    const int by = blockIdx.y;
    const float* A; const float* W; float* C; int bm;
    if (by < 16) { A = q; W = Wq; C = g_qp; bm = by * 64; }
    else         { A = k; W = Wk; C = g_kp; bm = (by - 16) * 64; }

    const int t  = threadIdx.x;
    const int bn = blockIdx.x * 64;
    const int tx = t % 16;
    const int ty = t / 16;

    u64 acc[4][2] = {};

    for (int k0 = 0; k0 < 256; k0 += 16) {
        {
            int row = t / 4, kk = (t % 4) * 4;
            float4 v = *(const float4*)(A + (size_t)(bm + row) * 256 + k0 + kk);
            As[kk + 0][row] = v.x;
            As[kk + 1][row] = v.y;
            As[kk + 2][row] = v.z;
            As[kk + 3][row] = v.w;
        }
        {
            int kk = t / 16, col = (t % 16) * 4;
            *(float4*)&Bs[kk][col] =
                *(const float4*)(W + (size_t)(k0 + kk) * 256 + bn + col);
        }
        __syncthreads();
        #pragma unroll
        for (int kk = 0; kk < 16; kk++) {
            ulonglong2 b2 = *(const ulonglong2*)&Bs[kk][tx * 4];
            float4 a4 = *(const float4*)&As[kk][ty * 4];
            float a[4] = {a4.x, a4.y, a4.z, a4.w};
            #pragma unroll
            for (int i = 0; i < 4; i++) {
                u64 ad = pack2(a[i], a[i]);
                acc[i][0] = ffma2(ad, b2.x, acc[i][0]);
                acc[i][1] = ffma2(ad, b2.y, acc[i][1]);
            }
        }
        __syncthreads();
    }
    #pragma unroll
    for (int i = 0; i < 4; i++) {
        float2 lo = unpack2(acc[i][0]);
        float2 hi = unpack2(acc[i][1]);
        *(float4*)(C + (size_t)(bm + ty * 4 + i) * 256 + bn + tx * 4) =
            make_float4(lo.x, lo.y, hi.x, hi.y);
    }
}

// ---------------------------------------------------------------------------
// Scores: s[b,q,k] = sum_h tanh(qp[b,q,h] + kp[b,k,h]) * wv[h]
// block = (b, 16 q, 64 k); MUFU-bound. Packed adds/FMAs cut issue slots.
// ---------------------------------------------------------------------------
__global__ __launch_bounds__(256) void scores_kernel(const float* __restrict__ wv) {
    __shared__ float qp_s[16][68];
    __shared__ float kp_s[64][68];
    __shared__ float wv_s[HH];

    const int t  = threadIdx.x;
    const int kt = blockIdx.x;
    const int qt = blockIdx.y;
    const int b  = blockIdx.z;
    const int kl = t % 64;
    const int qg = t / 64;

    if (t < HH) wv_s[t] = wv[t];

    const float* qp_base = g_qp + ((size_t)b * TQ + qt * 16) * HH;
    const float* kp_base = g_kp + ((size_t)b * TK + kt * 64) * HH;

    u64 acc[4] = {0ull, 0ull, 0ull, 0ull};

    for (int c = 0; c < 4; c++) {
        const int h0 = c * 64;
        __syncthreads();
        {
            int row = t / 16, col = (t % 16) * 4;
            *(float4*)&qp_s[row][col] =
                *(const float4*)(qp_base + (size_t)row * HH + h0 + col);
            #pragma unroll
            for (int j = 0; j < 4; j++) {
                int kr = row + j * 16;
                *(float4*)&kp_s[kr][col] =
                    *(const float4*)(kp_base + (size_t)kr * HH + h0 + col);
            }
        }
        __syncthreads();
        #pragma unroll
        for (int h4 = 0; h4 < 16; h4++) {
            ulonglong2 kv2 = *(const ulonglong2*)&kp_s[kl][h4 * 4];
            ulonglong2 wv2 = *(const ulonglong2*)&wv_s[h0 + h4 * 4];
            #pragma unroll
            for (int i = 0; i < 4; i++) {
                ulonglong2 qv2 = *(const ulonglong2*)&qp_s[qg * 4 + i][h4 * 4];
                float2 s0 = unpack2(fadd2(qv2.x, kv2.x));
                float2 s1 = unpack2(fadd2(qv2.y, kv2.y));
                u64 t0 = pack2(tanh_fast(s0.x), tanh_fast(s0.y));
                u64 t1 = pack2(tanh_fast(s1.x), tanh_fast(s1.y));
                acc[i] = ffma2(t0, wv2.x, acc[i]);
                acc[i] = ffma2(t1, wv2.y, acc[i]);
            }
        }
    }
    #pragma unroll
    for (int i = 0; i < 4; i++) {
        int q = qt * 16 + qg * 4 + i;
        g_attn[((size_t)b * TQ + q) * TK + kt * 64 + kl] = sum2(acc[i]);
    }
}

// ---------------------------------------------------------------------------
// Fused masked-softmax + AV: block = (qt of 8 q, b), 256 threads.
// Phase 1: load 8 score rows to smem. Phase 2: warp w softmaxes row w.
// Phase 3: out[b,q,:] = attn @ values with packed FFMA2.
// ---------------------------------------------------------------------------
__global__ __launch_bounds__(256) void softmax_av_kernel(
    const float* __restrict__ values, const int* __restrict__ valid_lens,
    float* __restrict__ out) {
    __shared__ float attn_s[8][512];   // 16 KB

    const int t  = threadIdx.x;
    const int qt = blockIdx.x;         // 0..15
    const int b  = blockIdx.y;
    const int vl = valid_lens[b];

    // load raw scores
    {
        const float4* src = (const float4*)(g_attn + ((size_t)b * TQ + qt * 8) * TK);
        float4* dst = (float4*)&attn_s[0][0];
        #pragma unroll
        for (int j = 0; j < 4; j++) dst[t + 256 * j] = src[t + 256 * j];
    }
    __syncthreads();

    // per-warp softmax: warp w owns row w; lane handles k = lane + 32*j
    {
        const int w    = t / 32;
        const int lane = t % 32;
        float* row = attn_s[w];
        float v[16];
        float mx = -INFINITY;
        #pragma unroll
        for (int j = 0; j < 16; j++) {
            int kk = lane + 32 * j;
            v[j] = row[kk];
            if (kk < vl) mx = fmaxf(mx, v[j]);
        }
        #pragma unroll
        for (int o = 16; o > 0; o >>= 1)
            mx = fmaxf(mx, __shfl_xor_sync(0xffffffff, mx, o));
        float sum = 0.f;
        #pragma unroll
        for (int j = 0; j < 16; j++) {
            int kk = lane + 32 * j;
            v[j] = (kk < vl) ? __expf(v[j] - mx) : 0.f;
            sum += v[j];
        }
        #pragma unroll
        for (int o = 16; o > 0; o >>= 1)
            sum += __shfl_xor_sync(0xffffffff, sum, o);
        float inv = 1.0f / sum;
        #pragma unroll
        for (int j = 0; j < 16; j++)
            row[lane + 32 * j] = v[j] * inv;
    }
    __syncthreads();

    // AV: dl = (t%64)*4 output cols, qg = t/64 -> q rows qg*2, qg*2+1
    const int dl = (t % 64) * 4;
    const int qg = t / 64;
    const float* vbase = values + (size_t)b * TK * DD;

    u64 acc0[2] = {0ull, 0ull};
    u64 acc1[2] = {0ull, 0ull};

    for (int k4 = 0; k4 < 128; k4++) {
        float4 a0 = *(const float4*)&attn_s[qg * 2 + 0][k4 * 4];
        float4 a1 = *(const float4*)&attn_s[qg * 2 + 1][k4 * 4];
        float av0[4] = {a0.x, a0.y, a0.z, a0.w};
        float av1[4] = {a1.x, a1.y, a1.z, a1.w};
        #pragma unroll
        for (int kk = 0; kk < 4; kk++) {
            ulonglong2 v2 = *(const ulonglong2*)(vbase + (size_t)(k4 * 4 + kk) * DD + dl);
            u64 a0d = pack2(av0[kk], av0[kk]);
            u64 a1d = pack2(av1[kk], av1[kk]);
            acc0[0] = ffma2(a0d, v2.x, acc0[0]);
            acc0[1] = ffma2(a0d, v2.y, acc0[1]);
            acc1[0] = ffma2(a1d, v2.x, acc1[0]);
            acc1[1] = ffma2(a1d, v2.y, acc1[1]);
        }
    }

    {
        int q = qt * 8 + qg * 2;
        float2 l0 = unpack2(acc0[0]), h0 = unpack2(acc0[1]);
        float2 l1 = unpack2(acc1[0]), h1 = unpack2(acc1[1]);
        *(float4*)(out + ((size_t)b * TQ + q) * DD + dl) =
            make_float4(l0.x, l0.y, h0.x, h0.y);
        *(float4*)(out + ((size_t)b * TQ + q + 1) * DD + dl) =
            make_float4(l1.x, l1.y, h1.x, h1.y);
    }
}

// ---------------------------------------------------------------------------
// Inputs (metadata order): queries, keys, values, valid_lens, Wq, Wk, wv
// ---------------------------------------------------------------------------
extern "C" void kernel_launch(void* const* d_in, const int* in_sizes, int n_in,
                              void* d_out, int out_size) {
    const float* queries    = (const float*)d_in[0];
    const float* keys       = (const float*)d_in[1];
    const float* values     = (const float*)d_in[2];
    const int*   valid_lens = (const int*)d_in[3];
    const float* Wq         = (const float*)d_in[4];
    const float* Wk         = (const float*)d_in[5];
    const float* wv         = (const float*)d_in[6];
    float*       out        = (float*)d_out;

    // both projections: 16 q-row blocks + 64 k-row blocks
    proj_kernel<<<dim3(4, 80), 256>>>(queries, keys, Wq, Wk);
    // scores
    scores_kernel<<<dim3(8, 8, 8), 256>>>(wv);
    // fused masked softmax + AV
    softmax_av_kernel<<<dim3(16, 8), 256>>>(values, valid_lens, out);
}

// round 3
// speedup vs baseline: 1.1535x; 1.0558x over previous
#include <cuda_runtime.h>
#include <math.h>

#define B  8
#define TQ 128
#define TK 512
#define DD 256
#define HH 256

// Scratch (no allocations allowed)
__device__ float g_qp[B * TQ * HH];     // 1 MB
__device__ float g_kp[B * TK * HH];     // 4 MB
__device__ float g_attn[B * TQ * TK];   // 2 MB (raw scores)

typedef unsigned long long u64;

__device__ __forceinline__ float tanh_fast(float x) {
    float y;
    asm("tanh.approx.f32 %0, %1;" : "=f"(y) : "f"(x));
    return y;
}
__device__ __forceinline__ u64 ffma2(u64 a, u64 b, u64 c) {
    u64 d;
    asm("fma.rn.f32x2 %0, %1, %2, %3;" : "=l"(d) : "l"(a), "l"(b), "l"(c));
    return d;
}
__device__ __forceinline__ u64 fadd2(u64 a, u64 b) {
    u64 d;
    asm("add.rn.f32x2 %0, %1, %2;" : "=l"(d) : "l"(a), "l"(b));
    return d;
}
__device__ __forceinline__ u64 pack2(float lo, float hi) {
    u64 r;
    asm("mov.b64 %0, {%1, %2};" : "=l"(r) : "f"(lo), "f"(hi));
    return r;
}
__device__ __forceinline__ float2 unpack2(u64 v) {
    float lo, hi;
    asm("mov.b64 {%0, %1}, %2;" : "=f"(lo), "=f"(hi) : "l"(v));
    return make_float2(lo, hi);
}
__device__ __forceinline__ float sum2(u64 v) {
    float2 f = unpack2(v);
    return f.x + f.y;
}

__device__ __forceinline__ unsigned smem_u32(const void* p) {
    return (unsigned)__cvta_generic_to_shared(p);
}
__device__ __forceinline__ void cp_async16(unsigned dst, const void* src) {
    asm volatile("cp.async.cg.shared.global [%0], [%1], 16;\n"
                 :: "r"(dst), "l"(src));
}
__device__ __forceinline__ void cp_commit() {
    asm volatile("cp.async.commit_group;\n");
}
template <int N>
__device__ __forceinline__ void cp_wait() {
    asm volatile("cp.async.wait_group %0;\n" :: "n"(N));
}

// ---------------------------------------------------------------------------
// Combined projection GEMM: q@Wq and k@Wk in one launch.
// 64x64 tile, BK=32, 256 threads, 4x4 micro-tile with FFMA2,
// cp.async double-buffered pipeline.
// ---------------------------------------------------------------------------
__global__ __launch_bounds__(256) void proj_kernel(
    const float* __restrict__ q, const float* __restrict__ k,
    const float* __restrict__ Wq, const float* __restrict__ Wk) {
    __shared__ float As[2][64][32];   // [buf][m][k]  8 KB/buf
    __shared__ float Bs[2][32][64];   // [buf][k][n]  8 KB/buf

    const int by = blockIdx.y;
    const float* A; const float* W; float* C; int bm;
    if (by < 16) { A = q; W = Wq; C = g_qp; bm = by * 64; }
    else         { A = k; W = Wk; C = g_kp; bm = (by - 16) * 64; }

    const int t  = threadIdx.x;
    const int bn = blockIdx.x * 64;
    const int tx = t % 16;
    const int ty = t / 16;

    // cp.async source/dest mapping (2 x 16B per tile per thread)
    const int a_m0 = t / 8,        a_k0 = (t % 8) * 4;          // seg t
    const int a_m1 = (t + 256) / 8, a_k1 = ((t + 256) % 8) * 4; // seg t+256
    const int b_k0 = t / 16,        b_n0 = (t % 16) * 4;
    const int b_k1 = (t + 256) / 16, b_n1 = ((t + 256) % 16) * 4;

    const float* Abase = A + (size_t)bm * 256;
    const float* Wbase = W + bn;

    unsigned sA[2], sB[2];
    sA[0] = smem_u32(&As[0][0][0]); sA[1] = smem_u32(&As[1][0][0]);
    sB[0] = smem_u32(&Bs[0][0][0]); sB[1] = smem_u32(&Bs[1][0][0]);

    #define LOAD_STAGE(buf, kt)                                                  \
        do {                                                                     \
            int _k0 = (kt) * 32;                                                 \
            cp_async16(sA[buf] + (a_m0 * 32 + a_k0) * 4,                         \
                       Abase + (size_t)a_m0 * 256 + _k0 + a_k0);                 \
            cp_async16(sA[buf] + (a_m1 * 32 + a_k1) * 4,                         \
                       Abase + (size_t)a_m1 * 256 + _k0 + a_k1);                 \
            cp_async16(sB[buf] + (b_k0 * 64 + b_n0) * 4,                         \
                       Wbase + (size_t)(_k0 + b_k0) * 256 + b_n0);               \
            cp_async16(sB[buf] + (b_k1 * 64 + b_n1) * 4,                         \
                       Wbase + (size_t)(_k0 + b_k1) * 256 + b_n1);               \
            cp_commit();                                                         \
        } while (0)

    u64 acc[4][2] = {};

    LOAD_STAGE(0, 0);

    #pragma unroll 1
    for (int kt = 0; kt < 8; kt++) {
        int buf = kt & 1;
        if (kt + 1 < 8) {
            LOAD_STAGE(buf ^ 1, kt + 1);
            cp_wait<1>();
        } else {
            cp_wait<0>();
        }
        __syncthreads();

        #pragma unroll
        for (int kk4 = 0; kk4 < 8; kk4++) {
            float4 a0 = *(const float4*)&As[buf][ty * 4 + 0][kk4 * 4];
            float4 a1 = *(const float4*)&As[buf][ty * 4 + 1][kk4 * 4];
            float4 a2 = *(const float4*)&As[buf][ty * 4 + 2][kk4 * 4];
            float4 a3 = *(const float4*)&As[buf][ty * 4 + 3][kk4 * 4];
            #pragma unroll
            for (int j = 0; j < 4; j++) {
                ulonglong2 b2 = *(const ulonglong2*)&Bs[buf][kk4 * 4 + j][tx * 4];
                float av[4] = {j == 0 ? a0.x : j == 1 ? a0.y : j == 2 ? a0.z : a0.w,
                               j == 0 ? a1.x : j == 1 ? a1.y : j == 2 ? a1.z : a1.w,
                               j == 0 ? a2.x : j == 1 ? a2.y : j == 2 ? a2.z : a2.w,
                               j == 0 ? a3.x : j == 1 ? a3.y : j == 2 ? a3.z : a3.w};
                #pragma unroll
                for (int i = 0; i < 4; i++) {
                    u64 ad = pack2(av[i], av[i]);
                    acc[i][0] = ffma2(ad, b2.x, acc[i][0]);
                    acc[i][1] = ffma2(ad, b2.y, acc[i][1]);
                }
            }
        }
        __syncthreads();
    }
    #undef LOAD_STAGE

    #pragma unroll
    for (int i = 0; i < 4; i++) {
        float2 lo = unpack2(acc[i][0]);
        float2 hi = unpack2(acc[i][1]);
        *(float4*)(C + (size_t)(bm + ty * 4 + i) * 256 + bn + tx * 4) =
            make_float4(lo.x, lo.y, hi.x, hi.y);
    }
}

// ---------------------------------------------------------------------------
// Scores: s[b,q,k] = sum_h tanh(qp[b,q,h] + kp[b,k,h]) * wv[h]
// block = (b, 16 q, 64 k); MUFU-bound.
// ---------------------------------------------------------------------------
__global__ __launch_bounds__(256) void scores_kernel(const float* __restrict__ wv) {
    __shared__ float qp_s[16][68];
    __shared__ float kp_s[64][68];
    __shared__ float wv_s[HH];

    const int t  = threadIdx.x;
    const int kt = blockIdx.x;
    const int qt = blockIdx.y;
    const int b  = blockIdx.z;
    const int kl = t % 64;
    const int qg = t / 64;

    if (t < HH) wv_s[t] = wv[t];

    const float* qp_base = g_qp + ((size_t)b * TQ + qt * 16) * HH;
    const float* kp_base = g_kp + ((size_t)b * TK + kt * 64) * HH;

    u64 acc[4] = {0ull, 0ull, 0ull, 0ull};

    for (int c = 0; c < 4; c++) {
        const int h0 = c * 64;
        __syncthreads();
        {
            int row = t / 16, col = (t % 16) * 4;
            *(float4*)&qp_s[row][col] =
                *(const float4*)(qp_base + (size_t)row * HH + h0 + col);
            #pragma unroll
            for (int j = 0; j < 4; j++) {
                int kr = row + j * 16;
                *(float4*)&kp_s[kr][col] =
                    *(const float4*)(kp_base + (size_t)kr * HH + h0 + col);
            }
        }
        __syncthreads();
        #pragma unroll
        for (int h4 = 0; h4 < 16; h4++) {
            ulonglong2 kv2 = *(const ulonglong2*)&kp_s[kl][h4 * 4];
            ulonglong2 wv2 = *(const ulonglong2*)&wv_s[h0 + h4 * 4];
            #pragma unroll
            for (int i = 0; i < 4; i++) {
                ulonglong2 qv2 = *(const ulonglong2*)&qp_s[qg * 4 + i][h4 * 4];
                float2 s0 = unpack2(fadd2(qv2.x, kv2.x));
                float2 s1 = unpack2(fadd2(qv2.y, kv2.y));
                u64 t0 = pack2(tanh_fast(s0.x), tanh_fast(s0.y));
                u64 t1 = pack2(tanh_fast(s1.x), tanh_fast(s1.y));
                acc[i] = ffma2(t0, wv2.x, acc[i]);
                acc[i] = ffma2(t1, wv2.y, acc[i]);
            }
        }
    }
    #pragma unroll
    for (int i = 0; i < 4; i++) {
        int q = qt * 16 + qg * 4 + i;
        g_attn[((size_t)b * TQ + q) * TK + kt * 64 + kl] = sum2(acc[i]);
    }
}

// ---------------------------------------------------------------------------
// Fused masked-softmax + AV: block = (qt of 8 q, b), 256 threads.
// ---------------------------------------------------------------------------
__global__ __launch_bounds__(256) void softmax_av_kernel(
    const float* __restrict__ values, const int* __restrict__ valid_lens,
    float* __restrict__ out) {
    __shared__ float attn_s[8][512];   // 16 KB

    const int t  = threadIdx.x;
    const int qt = blockIdx.x;         // 0..15
    const int b  = blockIdx.y;
    const int vl = valid_lens[b];

    {
        const float4* src = (const float4*)(g_attn + ((size_t)b * TQ + qt * 8) * TK);
        float4* dst = (float4*)&attn_s[0][0];
        #pragma unroll
        for (int j = 0; j < 4; j++) dst[t + 256 * j] = src[t + 256 * j];
    }
    __syncthreads();

    {
        const int w    = t / 32;
        const int lane = t % 32;
        float* row = attn_s[w];
        float v[16];
        float mx = -INFINITY;
        #pragma unroll
        for (int j = 0; j < 16; j++) {
            int kk = lane + 32 * j;
            v[j] = row[kk];
            if (kk < vl) mx = fmaxf(mx, v[j]);
        }
        #pragma unroll
        for (int o = 16; o > 0; o >>= 1)
            mx = fmaxf(mx, __shfl_xor_sync(0xffffffff, mx, o));
        float sum = 0.f;
        #pragma unroll
        for (int j = 0; j < 16; j++) {
            int kk = lane + 32 * j;
            v[j] = (kk < vl) ? __expf(v[j] - mx) : 0.f;
            sum += v[j];
        }
        #pragma unroll
        for (int o = 16; o > 0; o >>= 1)
            sum += __shfl_xor_sync(0xffffffff, sum, o);
        float inv = 1.0f / sum;
        #pragma unroll
        for (int j = 0; j < 16; j++)
            row[lane + 32 * j] = v[j] * inv;
    }
    __syncthreads();

    const int dl = (t % 64) * 4;
    const int qg = t / 64;
    const float* vbase = values + (size_t)b * TK * DD;

    u64 acc0[2] = {0ull, 0ull};
    u64 acc1[2] = {0ull, 0ull};

    for (int k4 = 0; k4 < 128; k4++) {
        float4 a0 = *(const float4*)&attn_s[qg * 2 + 0][k4 * 4];
        float4 a1 = *(const float4*)&attn_s[qg * 2 + 1][k4 * 4];
        float av0[4] = {a0.x, a0.y, a0.z, a0.w};
        float av1[4] = {a1.x, a1.y, a1.z, a1.w};
        #pragma unroll
        for (int kk = 0; kk < 4; kk++) {
            ulonglong2 v2 = *(const ulonglong2*)(vbase + (size_t)(k4 * 4 + kk) * DD + dl);
            u64 a0d = pack2(av0[kk], av0[kk]);
            u64 a1d = pack2(av1[kk], av1[kk]);
            acc0[0] = ffma2(a0d, v2.x, acc0[0]);
            acc0[1] = ffma2(a0d, v2.y, acc0[1]);
            acc1[0] = ffma2(a1d, v2.x, acc1[0]);
            acc1[1] = ffma2(a1d, v2.y, acc1[1]);
        }
    }

    {
        int q = qt * 8 + qg * 2;
        float2 l0 = unpack2(acc0[0]), h0 = unpack2(acc0[1]);
        float2 l1 = unpack2(acc1[0]), h1 = unpack2(acc1[1]);
        *(float4*)(out + ((size_t)b * TQ + q) * DD + dl) =
            make_float4(l0.x, l0.y, h0.x, h0.y);
        *(float4*)(out + ((size_t)b * TQ + q + 1) * DD + dl) =
            make_float4(l1.x, l1.y, h1.x, h1.y);
    }
}

// ---------------------------------------------------------------------------
// Inputs (metadata order): queries, keys, values, valid_lens, Wq, Wk, wv
// ---------------------------------------------------------------------------
extern "C" void kernel_launch(void* const* d_in, const int* in_sizes, int n_in,
                              void* d_out, int out_size) {
    const float* queries    = (const float*)d_in[0];
    const float* keys       = (const float*)d_in[1];
    const float* values     = (const float*)d_in[2];
    const int*   valid_lens = (const int*)d_in[3];
    const float* Wq         = (const float*)d_in[4];
    const float* Wk         = (const float*)d_in[5];
    const float* wv         = (const float*)d_in[6];
    float*       out        = (float*)d_out;

    proj_kernel<<<dim3(4, 80), 256>>>(queries, keys, Wq, Wk);
    scores_kernel<<<dim3(8, 8, 8), 256>>>(wv);
    softmax_av_kernel<<<dim3(16, 8), 256>>>(values, valid_lens, out);
}

// round 4
// speedup vs baseline: 1.4710x; 1.2752x over previous
#include <cuda_runtime.h>
#include <math.h>

#define B  8
#define TQ 128
#define TK 512
#define DD 256
#define HH 256

// Scratch (no allocations allowed)
__device__ float g_qp[B * TQ * HH];     // 1 MB
__device__ float g_kp[B * TK * HH];     // 4 MB (rows >= valid_lens[b] stay garbage — masked later)
__device__ float g_attn[B * TQ * TK];   // 2 MB (raw scores; masked cols garbage — masked later)

typedef unsigned long long u64;

__device__ __forceinline__ float tanh_fast(float x) {
    float y;
    asm("tanh.approx.f32 %0, %1;" : "=f"(y) : "f"(x));
    return y;
}
__device__ __forceinline__ u64 ffma2(u64 a, u64 b, u64 c) {
    u64 d;
    asm("fma.rn.f32x2 %0, %1, %2, %3;" : "=l"(d) : "l"(a), "l"(b), "l"(c));
    return d;
}
__device__ __forceinline__ u64 fadd2(u64 a, u64 b) {
    u64 d;
    asm("add.rn.f32x2 %0, %1, %2;" : "=l"(d) : "l"(a), "l"(b));
    return d;
}
__device__ __forceinline__ u64 pack2(float lo, float hi) {
    u64 r;
    asm("mov.b64 %0, {%1, %2};" : "=l"(r) : "f"(lo), "f"(hi));
    return r;
}
__device__ __forceinline__ float2 unpack2(u64 v) {
    float lo, hi;
    asm("mov.b64 {%0, %1}, %2;" : "=f"(lo), "=f"(hi) : "l"(v));
    return make_float2(lo, hi);
}
__device__ __forceinline__ float sum2(u64 v) {
    float2 f = unpack2(v);
    return f.x + f.y;
}

__device__ __forceinline__ unsigned smem_u32(const void* p) {
    return (unsigned)__cvta_generic_to_shared(p);
}
__device__ __forceinline__ void cp_async16(unsigned dst, const void* src) {
    asm volatile("cp.async.cg.shared.global [%0], [%1], 16;\n"
                 :: "r"(dst), "l"(src));
}
__device__ __forceinline__ void cp_commit() {
    asm volatile("cp.async.commit_group;\n");
}
template <int N>
__device__ __forceinline__ void cp_wait() {
    asm volatile("cp.async.wait_group %0;\n" :: "n"(N));
}

// ---------------------------------------------------------------------------
// Combined projection GEMM: q@Wq and k@Wk in one launch.
// 32x64 tile, BK=32, 128 threads, 4x4 micro-tile, FFMA2, cp.async double buf.
// k-row blocks whose rows are entirely masked (local >= vl[b]) exit early.
// ---------------------------------------------------------------------------
__global__ __launch_bounds__(128) void proj_kernel(
    const float* __restrict__ q, const float* __restrict__ k,
    const float* __restrict__ Wq, const float* __restrict__ Wk,
    const int* __restrict__ valid_lens) {
    __shared__ float As[2][32][32];   // [buf][m][k]  4 KB/buf
    __shared__ float Bs[2][32][64];   // [buf][k][n]  8 KB/buf

    const int by = blockIdx.y;
    const float* A; const float* W; float* C; int bm;
    if (by < 32) {
        A = q; W = Wq; C = g_qp; bm = by * 32;
    } else {
        int r = by - 32;                 // 0..127
        bm = r * 32;                     // row in [0, 4096)
        int b = bm >> 9;                 // batch
        int local = bm & 511;
        if (local >= valid_lens[b]) return;   // fully-masked k rows: skip
        A = k; W = Wk; C = g_kp;
    }

    const int t  = threadIdx.x;
    const int bn = blockIdx.x * 64;
    const int tx = t % 16;
    const int ty = t / 16;       // 0..7

    const float* Abase = A + (size_t)bm * 256;
    const float* Wbase = W + bn;

    unsigned sA[2], sB[2];
    sA[0] = smem_u32(&As[0][0][0]); sA[1] = smem_u32(&As[1][0][0]);
    sB[0] = smem_u32(&Bs[0][0][0]); sB[1] = smem_u32(&Bs[1][0][0]);

    #define LOAD_STAGE(buf, kt)                                                  \
        do {                                                                     \
            int _k0 = (kt) * 32;                                                 \
            {                                                                    \
                int u = t;                                                       \
                cp_async16(sA[buf] + ((u / 8) * 32 + (u % 8) * 4) * 4,           \
                           Abase + (size_t)(u / 8) * 256 + _k0 + (u % 8) * 4);   \
            }                                                                    \
            {                                                                    \
                int u = t + 128;                                                 \
                cp_async16(sA[buf] + ((u / 8) * 32 + (u % 8) * 4) * 4,           \
                           Abase + (size_t)(u / 8) * 256 + _k0 + (u % 8) * 4);   \
            }                                                                    \
            _Pragma("unroll")                                                    \
            for (int j = 0; j < 4; j++) {                                        \
                int u = t + 128 * j;                                             \
                cp_async16(sB[buf] + ((u / 16) * 64 + (u % 16) * 4) * 4,         \
                           Wbase + (size_t)(_k0 + u / 16) * 256 + (u % 16) * 4); \
            }                                                                    \
            cp_commit();                                                         \
        } while (0)

    u64 acc[4][2] = {};

    LOAD_STAGE(0, 0);

    #pragma unroll 1
    for (int kt = 0; kt < 8; kt++) {
        int buf = kt & 1;
        if (kt + 1 < 8) {
            LOAD_STAGE(buf ^ 1, kt + 1);
            cp_wait<1>();
        } else {
            cp_wait<0>();
        }
        __syncthreads();

        #pragma unroll
        for (int kk4 = 0; kk4 < 8; kk4++) {
            float4 a0 = *(const float4*)&As[buf][ty * 4 + 0][kk4 * 4];
            float4 a1 = *(const float4*)&As[buf][ty * 4 + 1][kk4 * 4];
            float4 a2 = *(const float4*)&As[buf][ty * 4 + 2][kk4 * 4];
            float4 a3 = *(const float4*)&As[buf][ty * 4 + 3][kk4 * 4];
            #pragma unroll
            for (int j = 0; j < 4; j++) {
                ulonglong2 b2 = *(const ulonglong2*)&Bs[buf][kk4 * 4 + j][tx * 4];
                float av[4] = {j == 0 ? a0.x : j == 1 ? a0.y : j == 2 ? a0.z : a0.w,
                               j == 0 ? a1.x : j == 1 ? a1.y : j == 2 ? a1.z : a1.w,
                               j == 0 ? a2.x : j == 1 ? a2.y : j == 2 ? a2.z : a2.w,
                               j == 0 ? a3.x : j == 1 ? a3.y : j == 2 ? a3.z : a3.w};
                #pragma unroll
                for (int i = 0; i < 4; i++) {
                    u64 ad = pack2(av[i], av[i]);
                    acc[i][0] = ffma2(ad, b2.x, acc[i][0]);
                    acc[i][1] = ffma2(ad, b2.y, acc[i][1]);
                }
            }
        }
        __syncthreads();
    }
    #undef LOAD_STAGE

    #pragma unroll
    for (int i = 0; i < 4; i++) {
        float2 lo = unpack2(acc[i][0]);
        float2 hi = unpack2(acc[i][1]);
        *(float4*)(C + (size_t)(bm + ty * 4 + i) * 256 + bn + tx * 4) =
            make_float4(lo.x, lo.y, hi.x, hi.y);
    }
}

// ---------------------------------------------------------------------------
// Scores: s[b,q,k] = sum_h tanh(qp[b,q,h] + kp[b,k,h]) * wv[h]
// block = (b, 16 q, 64 k); MUFU-tanh bound. Blocks whose whole k-tile is
// masked (kt*64 >= vl[b]) exit immediately — their g_attn stays garbage and
// is masked in the softmax.
// ---------------------------------------------------------------------------
__global__ __launch_bounds__(256) void scores_kernel(
    const float* __restrict__ wv, const int* __restrict__ valid_lens) {
    __shared__ float qp_s[16][68];
    __shared__ float kp_s[64][68];
    __shared__ float wv_s[HH];

    const int kt = blockIdx.x;
    const int qt = blockIdx.y;
    const int b  = blockIdx.z;
    if (kt * 64 >= valid_lens[b]) return;   // fully-masked tile

    const int t  = threadIdx.x;
    const int kl = t % 64;
    const int qg = t / 64;

    if (t < HH) wv_s[t] = wv[t];

    const float* qp_base = g_qp + ((size_t)b * TQ + qt * 16) * HH;
    const float* kp_base = g_kp + ((size_t)b * TK + kt * 64) * HH;

    u64 acc[4] = {0ull, 0ull, 0ull, 0ull};

    for (int c = 0; c < 4; c++) {
        const int h0 = c * 64;
        __syncthreads();
        {
            int row = t / 16, col = (t % 16) * 4;
            *(float4*)&qp_s[row][col] =
                *(const float4*)(qp_base + (size_t)row * HH + h0 + col);
            #pragma unroll
            for (int j = 0; j < 4; j++) {
                int kr = row + j * 16;
                *(float4*)&kp_s[kr][col] =
                    *(const float4*)(kp_base + (size_t)kr * HH + h0 + col);
            }
        }
        __syncthreads();
        #pragma unroll
        for (int h4 = 0; h4 < 16; h4++) {
            ulonglong2 kv2 = *(const ulonglong2*)&kp_s[kl][h4 * 4];
            ulonglong2 wv2 = *(const ulonglong2*)&wv_s[h0 + h4 * 4];
            #pragma unroll
            for (int i = 0; i < 4; i++) {
                ulonglong2 qv2 = *(const ulonglong2*)&qp_s[qg * 4 + i][h4 * 4];
                float2 s0 = unpack2(fadd2(qv2.x, kv2.x));
                float2 s1 = unpack2(fadd2(qv2.y, kv2.y));
                u64 t0 = pack2(tanh_fast(s0.x), tanh_fast(s0.y));
                u64 t1 = pack2(tanh_fast(s1.x), tanh_fast(s1.y));
                acc[i] = ffma2(t0, wv2.x, acc[i]);
                acc[i] = ffma2(t1, wv2.y, acc[i]);
            }
        }
    }
    #pragma unroll
    for (int i = 0; i < 4; i++) {
        int q = qt * 16 + qg * 4 + i;
        g_attn[((size_t)b * TQ + q) * TK + kt * 64 + kl] = sum2(acc[i]);
    }
}

// ---------------------------------------------------------------------------
// Fused masked-softmax + AV: block = (qt of 8 q, b), 256 threads.
// Softmax masks k >= vl (garbage-safe). AV loops only over valid k.
// ---------------------------------------------------------------------------
__global__ __launch_bounds__(256) void softmax_av_kernel(
    const float* __restrict__ values, const int* __restrict__ valid_lens,
    float* __restrict__ out) {
    __shared__ float attn_s[8][512];   // 16 KB

    const int t  = threadIdx.x;
    const int qt = blockIdx.x;         // 0..15
    const int b  = blockIdx.y;
    const int vl = valid_lens[b];

    {
        const float4* src = (const float4*)(g_attn + ((size_t)b * TQ + qt * 8) * TK);
        float4* dst = (float4*)&attn_s[0][0];
        #pragma unroll
        for (int j = 0; j < 4; j++) dst[t + 256 * j] = src[t + 256 * j];
    }
    __syncthreads();

    {
        const int w    = t / 32;
        const int lane = t % 32;
        float* row = attn_s[w];
        float v[16];
        float mx = -INFINITY;
        #pragma unroll
        for (int j = 0; j < 16; j++) {
            int kk = lane + 32 * j;
            v[j] = row[kk];
            if (kk < vl) mx = fmaxf(mx, v[j]);
        }
        #pragma unroll
        for (int o = 16; o > 0; o >>= 1)
            mx = fmaxf(mx, __shfl_xor_sync(0xffffffff, mx, o));
        float sum = 0.f;
        #pragma unroll
        for (int j = 0; j < 16; j++) {
            int kk = lane + 32 * j;
            v[j] = (kk < vl) ? __expf(v[j] - mx) : 0.f;
            sum += v[j];
        }
        #pragma unroll
        for (int o = 16; o > 0; o >>= 1)
            sum += __shfl_xor_sync(0xffffffff, sum, o);
        float inv = 1.0f / sum;
        #pragma unroll
        for (int j = 0; j < 16; j++)
            row[lane + 32 * j] = v[j] * inv;
    }
    __syncthreads();

    const int dl = (t % 64) * 4;
    const int qg = t / 64;
    const float* vbase = values + (size_t)b * TK * DD;

    u64 acc0[2] = {0ull, 0ull};
    u64 acc1[2] = {0ull, 0ull};

    const int k4max = (vl + 3) >> 2;   // attn beyond vl is exactly 0

    for (int k4 = 0; k4 < k4max; k4++) {
        float4 a0 = *(const float4*)&attn_s[qg * 2 + 0][k4 * 4];
        float4 a1 = *(const float4*)&attn_s[qg * 2 + 1][k4 * 4];
        float av0[4] = {a0.x, a0.y, a0.z, a0.w};
        float av1[4] = {a1.x, a1.y, a1.z, a1.w};
        #pragma unroll
        for (int kk = 0; kk < 4; kk++) {
            ulonglong2 v2 = *(const ulonglong2*)(vbase + (size_t)(k4 * 4 + kk) * DD + dl);
            u64 a0d = pack2(av0[kk], av0[kk]);
            u64 a1d = pack2(av1[kk], av1[kk]);
            acc0[0] = ffma2(a0d, v2.x, acc0[0]);
            acc0[1] = ffma2(a0d, v2.y, acc0[1]);
            acc1[0] = ffma2(a1d, v2.x, acc1[0]);
            acc1[1] = ffma2(a1d, v2.y, acc1[1]);
        }
    }

    {
        int q = qt * 8 + qg * 2;
        float2 l0 = unpack2(acc0[0]), h0 = unpack2(acc0[1]);
        float2 l1 = unpack2(acc1[0]), h1 = unpack2(acc1[1]);
        *(float4*)(out + ((size_t)b * TQ + q) * DD + dl) =
            make_float4(l0.x, l0.y, h0.x, h0.y);
        *(float4*)(out + ((size_t)b * TQ + q + 1) * DD + dl) =
            make_float4(l1.x, l1.y, h1.x, h1.y);
    }
}

// ---------------------------------------------------------------------------
// Inputs (metadata order): queries, keys, values, valid_lens, Wq, Wk, wv
// ---------------------------------------------------------------------------
extern "C" void kernel_launch(void* const* d_in, const int* in_sizes, int n_in,
                              void* d_out, int out_size) {
    const float* queries    = (const float*)d_in[0];
    const float* keys       = (const float*)d_in[1];
    const float* values     = (const float*)d_in[2];
    const int*   valid_lens = (const int*)d_in[3];
    const float* Wq         = (const float*)d_in[4];
    const float* Wk         = (const float*)d_in[5];
    const float* wv         = (const float*)d_in[6];
    float*       out        = (float*)d_out;

    // projections: 32 q-row blocks + 128 k-row blocks (k blocks skip if masked)
    proj_kernel<<<dim3(4, 160), 128>>>(queries, keys, Wq, Wk, valid_lens);
    // scores (masked k-tiles skipped)
    scores_kernel<<<dim3(8, 8, 8), 256>>>(wv, valid_lens);
    // fused masked softmax + AV (valid-k bounded)
    softmax_av_kernel<<<dim3(16, 8), 256>>>(values, valid_lens, out);
}